// round 12
// baseline (speedup 1.0000x reference)
#include <cuda_runtime.h>
#include <cuda_fp16.h>
#include <math.h>

#define Bn 1024
#define Ln 64
#define Hn 512
#define NCTA 128
#define NTHREADS 256

// fp16 ping-pong state; fp16 history. Weights live in per-CTA resident SMEM.
__device__ __half g_S16[2][4][Bn][Hn];   // 8 MB
__device__ __half g_h16[Ln][Bn][Hn];     // 64 MB layer-3 outputs
__device__ float  g_lp[8][Bn];           // per-t-chunk partial log-probs
__device__ unsigned g_count;
__device__ volatile unsigned g_gen;

// Dynamic smem layout:
//   Wres: 1024 rows x 72 halfs (rows 0-511 = Wc_s slice, 512-1023 = Win_{s-1} slice)
//   Asm : 2 stages x 256 rows x 40 halfs
#define WPITCH 72
#define APITCH 40
#define W_HALFS (1024 * WPITCH)              // 73728
#define A_STAGE_HALFS (256 * APITCH)         // 10240
#define SMEM_BYTES ((W_HALFS + 2 * A_STAGE_HALFS) * 2)   // 188416 B

// ---------------------------------------------------------------------------
__device__ __forceinline__ void cp16(void* dst, const void* src) {
    unsigned d = (unsigned)__cvta_generic_to_shared(dst);
    asm volatile("cp.async.cg.shared.global [%0], [%1], 16;" :: "r"(d), "l"(src));
}
__device__ __forceinline__ void cp_commit() {
    asm volatile("cp.async.commit_group;" ::: "memory");
}
__device__ __forceinline__ void cp_wait0() {
    asm volatile("cp.async.wait_group 0;" ::: "memory");
}
__device__ __forceinline__ void ldsm4(unsigned r[4], const void* p) {
    unsigned a = (unsigned)__cvta_generic_to_shared(p);
    asm volatile("ldmatrix.sync.aligned.m8n8.x4.shared.b16 {%0,%1,%2,%3}, [%4];"
                 : "=r"(r[0]), "=r"(r[1]), "=r"(r[2]), "=r"(r[3]) : "r"(a));
}
__device__ __forceinline__ void ldsm4t(unsigned r[4], const void* p) {
    unsigned a = (unsigned)__cvta_generic_to_shared(p);
    asm volatile("ldmatrix.sync.aligned.m8n8.x4.trans.shared.b16 {%0,%1,%2,%3}, [%4];"
                 : "=r"(r[0]), "=r"(r[1]), "=r"(r[2]), "=r"(r[3]) : "r"(a));
}
__device__ __forceinline__ void mma_f16(float c[4], const unsigned a[4],
                                        unsigned b0, unsigned b1) {
    asm volatile(
        "mma.sync.aligned.m16n8k16.row.col.f32.f16.f16.f32 "
        "{%0,%1,%2,%3}, {%4,%5,%6,%7}, {%8,%9}, {%0,%1,%2,%3};"
        : "+f"(c[0]), "+f"(c[1]), "+f"(c[2]), "+f"(c[3])
        : "r"(a[0]), "r"(a[1]), "r"(a[2]), "r"(a[3]), "r"(b0), "r"(b1));
}

// Global barrier: 128 CTAs, 1/SM, all co-resident.
__device__ __forceinline__ void gbar(unsigned target) {
    __syncthreads();
    if (threadIdx.x == 0) {
        __threadfence();
        unsigned t = atomicAdd(&g_count, 1);
        if (t == NCTA - 1) {
            atomicExch(&g_count, 0);
            __threadfence();
            g_gen = target;
        } else {
            while ((int)(g_gen - target) < 0) {}
            __threadfence();
        }
    }
    __syncthreads();
}

// Stage one A chunk (256 rows x 32 halfs = 16KB). One row per thread, 4 cp16.
template <bool DUAL>
__device__ __forceinline__ void stage_a(
    __half* Asm, int st, int cc,
    const __half* A1, const __half* A2, int m0, int tid)
{
    const __half* Ap = (DUAL && cc >= 16) ? A2 : A1;
    const int kc = (cc & 15) * 32;
    const __half* src = Ap + (m0 + tid) * Hn + kc;
    __half* dst = Asm + st * A_STAGE_HALFS + tid * APITCH;
    cp16(dst,      src);
    cp16(dst + 8,  src + 8);
    cp16(dst + 16, src + 16);
    cp16(dst + 24, src + 24);
}

// One 256x64 job: C = elu(A1@W1 [+ A2@W2] + bias [+ Win0 one-hot row]).
// Weights resident in SMEM (Wres); only A streamed. fp32 accumulate.
template <bool DUAL, bool LAYER0, bool STORE>
__device__ __forceinline__ void do_job(
    const __half* Wres, __half* Asm, int t,
    const __half* A1, const __half* A2,
    const float* bias, const int* x, const float* Win0,
    __half* Cout, int m0, int n0)
{
    const int tid  = threadIdx.x;
    const int warp = tid >> 5, lane = tid & 31;
    const int mw = warp >> 1;           // 4 blocks of 64 rows
    const int nw = warp & 1;            // 2 blocks of 32 cols
    const int quad = lane >> 2, qt = lane & 3;
    const int lrow = lane & 15, lhi = (lane >> 4) << 3;

    float acc[4][4][4];
#pragma unroll
    for (int a = 0; a < 4; a++)
#pragma unroll
        for (int b = 0; b < 4; b++)
#pragma unroll
            for (int v = 0; v < 4; v++) acc[a][b][v] = 0.f;

    const int NCH = DUAL ? 32 : 16;
    stage_a<DUAL>(Asm, 0, 0, A1, A2, m0, tid);
    cp_commit();

    for (int cc = 0; cc < NCH; cc++) {
        cp_wait0();
        __syncthreads();
        const int st = cc & 1;
        if (cc + 1 < NCH) {
            stage_a<DUAL>(Asm, st ^ 1, cc + 1, A1, A2, m0, tid);
        }
        cp_commit();

        const int ph = (DUAL && cc >= 16) ? 1 : 0;
        const int kc = (cc & 15) * 32;
        const __half* Ab = Asm + st * A_STAGE_HALFS;
        const __half* Bb = Wres + (ph * 512 + kc) * WPITCH;

#pragma unroll
        for (int k16 = 0; k16 < 32; k16 += 16) {
            unsigned a[4][4];
#pragma unroll
            for (int ma = 0; ma < 4; ma++)
                ldsm4(a[ma], Ab + (mw * 64 + ma * 16 + lrow) * APITCH + k16 + lhi);
            unsigned b0[4], b1[4];
            ldsm4t(b0, Bb + (k16 + lrow) * WPITCH + nw * 32 + lhi);
            ldsm4t(b1, Bb + (k16 + lrow) * WPITCH + nw * 32 + 16 + lhi);
#pragma unroll
            for (int ma = 0; ma < 4; ma++) {
                mma_f16(acc[ma][0], a[ma], b0[0], b0[1]);
                mma_f16(acc[ma][1], a[ma], b0[2], b0[3]);
                mma_f16(acc[ma][2], a[ma], b1[0], b1[1]);
                mma_f16(acc[ma][3], a[ma], b1[2], b1[3]);
            }
        }
    }

    // epilogue: + bias (+ Win0[x[t-1]] row for layer 0), ELU, store
#pragma unroll
    for (int ma = 0; ma < 4; ma++) {
        const int r0 = m0 + mw * 64 + ma * 16 + quad;
        const int r1 = r0 + 8;
        int idx0 = 0, idx1 = 0;
        const bool l0add = LAYER0 && (t > 0);
        if (l0add) {
            idx0 = x[r0 * Ln + (t - 1)];
            idx1 = x[r1 * Ln + (t - 1)];
        }
#pragma unroll
        for (int nb = 0; nb < 4; nb++) {
            const int col = n0 + nw * 32 + nb * 8 + 2 * qt;
            const float2 bv = *reinterpret_cast<const float2*>(&bias[col]);
            float2 w0 = make_float2(0.f, 0.f), w1 = make_float2(0.f, 0.f);
            if (l0add) {
                w0 = *reinterpret_cast<const float2*>(&Win0[idx0 * Hn + col]);
                w1 = *reinterpret_cast<const float2*>(&Win0[idx1 * Hn + col]);
            }
            float v0 = acc[ma][nb][0] + bv.x + w0.x;
            float v1 = acc[ma][nb][1] + bv.y + w0.y;
            float v2 = acc[ma][nb][2] + bv.x + w1.x;
            float v3 = acc[ma][nb][3] + bv.y + w1.y;
            v0 = (v0 > 0.f) ? v0 : expm1f(v0);
            v1 = (v1 > 0.f) ? v1 : expm1f(v1);
            v2 = (v2 > 0.f) ? v2 : expm1f(v2);
            v3 = (v3 > 0.f) ? v3 : expm1f(v3);
            const __half2 p01 = __floats2half2_rn(v0, v1);
            const __half2 p23 = __floats2half2_rn(v2, v3);
            *reinterpret_cast<__half2*>(&Cout[r0 * Hn + col]) = p01;
            *reinterpret_cast<__half2*>(&Cout[r1 * Hn + col]) = p23;
            if (STORE) {
                *reinterpret_cast<__half2*>(&g_h16[t][r0][col]) = p01;
                *reinterpret_cast<__half2*>(&g_h16[t][r1][col]) = p23;
            }
        }
    }
}

// ---------------------------------------------------------------------------
__global__ void __launch_bounds__(NTHREADS, 1) rnn_persistent(
    const int*   __restrict__ x,         // [B][L]
    const float* __restrict__ Win0,      // [2][H]
    const float* __restrict__ Win_rest,  // [3][H][H]
    const float* __restrict__ Wc,        // [4][H][H]
    const float* __restrict__ bc)        // [4][H]
{
    extern __shared__ __align__(16) __half dsm[];
    __half* Wres = dsm;
    __half* Asm  = dsm + W_HALFS;

    const int tid  = threadIdx.x;
    const int cta  = blockIdx.x;
    const int gtid = cta * NTHREADS + tid;

    const int slot = cta >> 5;             // 0..3 == pinned layer j
    const int tile = cta & 31;             // 32 tiles of 256x64
    const int m0 = (tile >> 3) * 256;      // 4 m-tiles
    const int n0 = (tile & 7) * 64;        // 8 n-tiles

    unsigned base = g_gen;                 // stable until first barrier releases
    unsigned bar  = 0;

    // --- prologue: resident weights into SMEM (layer = slot), zero state ----
    {
        const float* W1src = Wc + slot * Hn * Hn;
        for (int i = tid; i < 512 * 64; i += NTHREADS) {
            const int k = i >> 6, n = i & 63;
            Wres[k * WPITCH + n] = __float2half_rn(W1src[k * Hn + n0 + n]);
        }
        if (slot > 0) {
            const float* W2src = Win_rest + (slot - 1) * Hn * Hn;
            for (int i = tid; i < 512 * 64; i += NTHREADS) {
                const int k = i >> 6, n = i & 63;
                Wres[(512 + k) * WPITCH + n] = __float2half_rn(W2src[k * Hn + n0 + n]);
            }
        }
        uint4* z = reinterpret_cast<uint4*>(&g_S16[0][0][0][0]);
        const uint4 z4 = make_uint4(0u, 0u, 0u, 0u);
        for (int i = gtid; i < 2 * 4 * Bn * Hn * 2 / 16; i += NCTA * NTHREADS)
            z[i] = z4;
    }
    gbar(base + (++bar));

    // --- wavefront: phase w, slot s computes (j=s, t=w-s) if 0<=t<64 --------
    for (int w = 0; w < Ln + 3; w++) {
        const int t = w - slot;
        if (t >= 0 && t < Ln) {
            const int pin = t & 1, pout = pin ^ 1;
            const __half* A1 = &g_S16[pin][slot][0][0];
            const __half* A2 = (slot > 0) ? &g_S16[pout][slot - 1][0][0] : A1;
            const float* bias = bc + slot * Hn;
            __half* Cout = &g_S16[pout][slot][0][0];
            switch (slot) {
                case 0:
                    do_job<false, true, false>(Wres, Asm, t, A1, A2, bias, x, Win0, Cout, m0, n0);
                    break;
                case 3:
                    do_job<true, false, true>(Wres, Asm, t, A1, A2, bias, x, Win0, Cout, m0, n0);
                    break;
                default:
                    do_job<true, false, false>(Wres, Asm, t, A1, A2, bias, x, Win0, Cout, m0, n0);
                    break;
            }
        }
        gbar(base + (++bar));
    }
}

// ---------------------------------------------------------------------------
// Log-prob partials: warp (b, tc) handles 8 timesteps, writes g_lp[tc][b].
// ---------------------------------------------------------------------------
__global__ void logp_part(const float* __restrict__ Wout,  // [H][2]
                          const float* __restrict__ bout,  // [2]
                          const int*   __restrict__ xsym)  // [B][L]
{
    const int gw   = (blockIdx.x * blockDim.x + threadIdx.x) >> 5;
    const int lane = threadIdx.x & 31;
    const int b  = gw >> 3;
    const int tc = gw & 7;
    if (b >= Bn) return;

    float w0[16], w1[16];
#pragma unroll
    for (int i = 0; i < 8; i++) {
        const int k = lane * 2 + 64 * i;
        w0[2 * i]     = Wout[k * 2 + 0];
        w1[2 * i]     = Wout[k * 2 + 1];
        w0[2 * i + 1] = Wout[(k + 1) * 2 + 0];
        w1[2 * i + 1] = Wout[(k + 1) * 2 + 1];
    }
    const float b0 = bout[0], b1 = bout[1];

    float acc = 0.f;
#pragma unroll
    for (int tt = 0; tt < 8; tt++) {
        const int t = tc * 8 + tt;
        const __half* h = &g_h16[t][b][0];
        float s0 = 0.f, s1 = 0.f;
#pragma unroll
        for (int i = 0; i < 8; i++) {
            const __half2 hv = *reinterpret_cast<const __half2*>(&h[lane * 2 + 64 * i]);
            const float h0 = __half2float(hv.x);
            const float h1 = __half2float(hv.y);
            s0 += h0 * w0[2 * i] + h1 * w0[2 * i + 1];
            s1 += h0 * w1[2 * i] + h1 * w1[2 * i + 1];
        }
#pragma unroll
        for (int off = 16; off > 0; off >>= 1) {
            s0 += __shfl_xor_sync(0xffffffffu, s0, off);
            s1 += __shfl_xor_sync(0xffffffffu, s1, off);
        }
        s0 += b0; s1 += b1;
        const float m   = fmaxf(s0, s1);
        const float lse = m + logf(expf(s0 - m) + expf(s1 - m));
        const float sel = (xsym[b * Ln + t] == 0) ? s0 : s1;
        acc += sel - lse;
    }
    if (lane == 0) g_lp[tc][b] = acc;
}

// Deterministic final sum: out[b] = 0.5 * sum_tc g_lp[tc][b]
__global__ void logp_sum(float* __restrict__ out) {
    const int b = blockIdx.x * blockDim.x + threadIdx.x;
    if (b >= Bn) return;
    float s = 0.f;
#pragma unroll
    for (int tc = 0; tc < 8; tc++) s += g_lp[tc][b];
    out[b] = 0.5f * s;
}

// ---------------------------------------------------------------------------
extern "C" void kernel_launch(void* const* d_in, const int* in_sizes, int n_in,
                              void* d_out, int out_size) {
    (void)in_sizes; (void)n_in; (void)out_size;
    const int*   x        = (const int*)  d_in[0];  // [B, L]
    const float* Win0     = (const float*)d_in[1];  // [2, H]
    const float* Win_rest = (const float*)d_in[2];  // [3, H, H]
    const float* Wc       = (const float*)d_in[3];  // [4, H, H]
    const float* bc       = (const float*)d_in[4];  // [4, H]
    const float* Wout     = (const float*)d_in[5];  // [H, 2]
    const float* bout     = (const float*)d_in[6];  // [2]
    float* out = (float*)d_out;                     // [B]

    cudaFuncSetAttribute(rnn_persistent,
                         cudaFuncAttributeMaxDynamicSharedMemorySize, SMEM_BYTES);

    rnn_persistent<<<NCTA, NTHREADS, SMEM_BYTES>>>(x, Win0, Win_rest, Wc, bc);
    logp_part<<<(Bn * 8) / 8, 256>>>(Wout, bout, x);   // 1024 blocks, 8 warps each
    logp_sum<<<Bn / 256, 256>>>(out);
}

// round 13
// speedup vs baseline: 1.2990x; 1.2990x over previous
#include <cuda_runtime.h>
#include <cuda_fp16.h>
#include <math.h>

#define Bn 1024
#define Ln 64
#define Hn 512
#define NCTA 256
#define NTHREADS 256

// fp16 ping-pong state + fp16 weights (converted once/launch), fp16 history.
__device__ __half g_S16[2][4][Bn][Hn];   // 8 MB
__device__ __half g_W16[7][Hn][Hn];      // [0..3]=Wc, [4..6]=Win_rest, [k][n] layout
__device__ __half g_h16[Ln][Bn][Hn];     // 64 MB layer-3 outputs
__device__ float  g_lp[8][Bn];           // per-t-chunk partial log-probs
__device__ unsigned g_flags[NCTA];       // per-CTA arrival generations (no atomics)
__device__ volatile unsigned g_gen;

struct Smem {
    __half A[2][128][40];   // 128x32 tile, pitch 80B (LDSM conflict-free)
    __half B[2][32][72];    // 32x64 tile,  pitch 144B (LDSM conflict-free)
};                          // 29696 B static -> 2 CTAs/SM

// ---------------------------------------------------------------------------
__device__ __forceinline__ void cp16(void* dst, const void* src) {
    unsigned d = (unsigned)__cvta_generic_to_shared(dst);
    asm volatile("cp.async.cg.shared.global [%0], [%1], 16;" :: "r"(d), "l"(src));
}
__device__ __forceinline__ void cp_commit() {
    asm volatile("cp.async.commit_group;" ::: "memory");
}
__device__ __forceinline__ void cp_wait0() {
    asm volatile("cp.async.wait_group 0;" ::: "memory");
}
__device__ __forceinline__ void ldsm4(unsigned r[4], const void* p) {
    unsigned a = (unsigned)__cvta_generic_to_shared(p);
    asm volatile("ldmatrix.sync.aligned.m8n8.x4.shared.b16 {%0,%1,%2,%3}, [%4];"
                 : "=r"(r[0]), "=r"(r[1]), "=r"(r[2]), "=r"(r[3]) : "r"(a));
}
__device__ __forceinline__ void ldsm4t(unsigned r[4], const void* p) {
    unsigned a = (unsigned)__cvta_generic_to_shared(p);
    asm volatile("ldmatrix.sync.aligned.m8n8.x4.trans.shared.b16 {%0,%1,%2,%3}, [%4];"
                 : "=r"(r[0]), "=r"(r[1]), "=r"(r[2]), "=r"(r[3]) : "r"(a));
}
__device__ __forceinline__ void mma_f16(float c[4], const unsigned a[4],
                                        unsigned b0, unsigned b1) {
    asm volatile(
        "mma.sync.aligned.m16n8k16.row.col.f32.f16.f16.f32 "
        "{%0,%1,%2,%3}, {%4,%5,%6,%7}, {%8,%9}, {%0,%1,%2,%3};"
        : "+f"(c[0]), "+f"(c[1]), "+f"(c[2]), "+f"(c[3])
        : "r"(a[0]), "r"(a[1]), "r"(a[2]), "r"(a[3]), "r"(b0), "r"(b1));
}

// Global barrier without same-address atomics:
// arrive = per-CTA flag store (parallel in LTS); CTA 0 gathers and releases.
__device__ __forceinline__ void gbar(unsigned target) {
    __syncthreads();
    if (threadIdx.x == 0) {
        __threadfence();                                     // publish my writes
        *(volatile unsigned*)&g_flags[blockIdx.x] = target;  // arrive
    }
    if (blockIdx.x == 0) {
        // NTHREADS == NCTA: thread i polls CTA i's flag.
        volatile unsigned* f = (volatile unsigned*)g_flags;
        while ((int)(f[threadIdx.x] - target) < 0) {}
        __syncthreads();                                     // all flags seen
        if (threadIdx.x == 0) {
            __threadfence();
            g_gen = target;                                  // release
        }
        __syncthreads();
    } else {
        if (threadIdx.x == 0) {
            while ((int)(g_gen - target) < 0) {}
            __threadfence();
        }
        __syncthreads();
    }
}

// Stage one BK=32 chunk (A: 128x32 = 64B/row, B: 32x64 = 128B/row). 3 cp16/thread.
template <bool DUAL>
__device__ __forceinline__ void stage_chunk(
    Smem* sm, int st, int cc,
    const __half* A1, const __half* A2,
    const __half* W1, const __half* W2,
    int m0, int n0, int tid)
{
    const bool ph = DUAL && (cc >= 16);
    const __half* As = ph ? A2 : A1;
    const __half* Ws = ph ? W2 : W1;
    const int kc = (cc & 15) * 32;

    const int ar  = tid >> 1;              // 0..127
    const int asg = (tid & 1) * 16;        // halfs 0 or 16
    cp16(&sm->A[st][ar][asg],     As + (m0 + ar) * Hn + kc + asg);
    cp16(&sm->A[st][ar][asg + 8], As + (m0 + ar) * Hn + kc + asg + 8);

    const int br = tid >> 3;               // 0..31
    const int bs = (tid & 7) * 8;          // halfs 0..56
    cp16(&sm->B[st][br][bs], Ws + (kc + br) * Hn + n0 + bs);
}

// One 128x64 job: C = elu(A1@W1 [+ A2@W2] + bias [+ Win0 one-hot row]).
// Warps: mw = warp>>1 (4 x 32 rows), nw = warp&1 (2 x 32 cols).
template <bool DUAL, bool LAYER0, bool STORE>
__device__ __forceinline__ void do_job(
    Smem* sm, int t,
    const __half* A1, const __half* A2,
    const __half* W1, const __half* W2,
    const float* bias, const int* x, const float* Win0,
    __half* Cout, int m0, int n0)
{
    const int tid  = threadIdx.x;
    const int warp = tid >> 5, lane = tid & 31;
    const int mw = warp >> 1;
    const int nw = warp & 1;
    const int quad = lane >> 2, qt = lane & 3;
    const int lrow = lane & 15, lhi = (lane >> 4) << 3;

    float acc[2][4][4];
#pragma unroll
    for (int a = 0; a < 2; a++)
#pragma unroll
        for (int b = 0; b < 4; b++)
#pragma unroll
            for (int v = 0; v < 4; v++) acc[a][b][v] = 0.f;

    const int NCH = DUAL ? 32 : 16;
    stage_chunk<DUAL>(sm, 0, 0, A1, A2, W1, W2, m0, n0, tid);
    cp_commit();

    for (int cc = 0; cc < NCH; cc++) {
        cp_wait0();
        __syncthreads();
        const int st = cc & 1;
        if (cc + 1 < NCH)
            stage_chunk<DUAL>(sm, st ^ 1, cc + 1, A1, A2, W1, W2, m0, n0, tid);
        cp_commit();

#pragma unroll
        for (int k16 = 0; k16 < 32; k16 += 16) {
            unsigned a[2][4];
            ldsm4(a[0], &sm->A[st][mw * 32 + lrow][k16 + lhi]);
            ldsm4(a[1], &sm->A[st][mw * 32 + 16 + lrow][k16 + lhi]);
            unsigned b0[4], b1[4];
            ldsm4t(b0, &sm->B[st][k16 + lrow][nw * 32 + lhi]);
            ldsm4t(b1, &sm->B[st][k16 + lrow][nw * 32 + 16 + lhi]);
#pragma unroll
            for (int ma = 0; ma < 2; ma++) {
                mma_f16(acc[ma][0], a[ma], b0[0], b0[1]);
                mma_f16(acc[ma][1], a[ma], b0[2], b0[3]);
                mma_f16(acc[ma][2], a[ma], b1[0], b1[1]);
                mma_f16(acc[ma][3], a[ma], b1[2], b1[3]);
            }
        }
    }

    // epilogue: + bias (+ Win0[x[t-1]] row for layer 0), ELU, store
#pragma unroll
    for (int ma = 0; ma < 2; ma++) {
        const int r0 = m0 + mw * 32 + ma * 16 + quad;
        const int r1 = r0 + 8;
        int idx0 = 0, idx1 = 0;
        const bool l0add = LAYER0 && (t > 0);
        if (l0add) {
            idx0 = x[r0 * Ln + (t - 1)];
            idx1 = x[r1 * Ln + (t - 1)];
        }
#pragma unroll
        for (int nb = 0; nb < 4; nb++) {
            const int col = n0 + nw * 32 + nb * 8 + 2 * qt;
            const float2 bv = *reinterpret_cast<const float2*>(&bias[col]);
            float2 w0 = make_float2(0.f, 0.f), w1 = make_float2(0.f, 0.f);
            if (l0add) {
                w0 = *reinterpret_cast<const float2*>(&Win0[idx0 * Hn + col]);
                w1 = *reinterpret_cast<const float2*>(&Win0[idx1 * Hn + col]);
            }
            float v0 = acc[ma][nb][0] + bv.x + w0.x;
            float v1 = acc[ma][nb][1] + bv.y + w0.y;
            float v2 = acc[ma][nb][2] + bv.x + w1.x;
            float v3 = acc[ma][nb][3] + bv.y + w1.y;
            v0 = (v0 > 0.f) ? v0 : expm1f(v0);
            v1 = (v1 > 0.f) ? v1 : expm1f(v1);
            v2 = (v2 > 0.f) ? v2 : expm1f(v2);
            v3 = (v3 > 0.f) ? v3 : expm1f(v3);
            const __half2 p01 = __floats2half2_rn(v0, v1);
            const __half2 p23 = __floats2half2_rn(v2, v3);
            *reinterpret_cast<__half2*>(&Cout[r0 * Hn + col]) = p01;
            *reinterpret_cast<__half2*>(&Cout[r1 * Hn + col]) = p23;
            if (STORE) {
                *reinterpret_cast<__half2*>(&g_h16[t][r0][col]) = p01;
                *reinterpret_cast<__half2*>(&g_h16[t][r1][col]) = p23;
            }
        }
    }
}

// ---------------------------------------------------------------------------
__global__ void __launch_bounds__(NTHREADS, 2) rnn_persistent(
    const int*   __restrict__ x,         // [B][L]
    const float* __restrict__ Win0,      // [2][H]
    const float* __restrict__ Win_rest,  // [3][H][H]
    const float* __restrict__ Wc,        // [4][H][H]
    const float* __restrict__ bc)        // [4][H]
{
    __shared__ __align__(16) Smem sm;

    const int tid  = threadIdx.x;
    const int cta  = blockIdx.x;
    const int gtid = cta * NTHREADS + tid;

    unsigned base = g_gen;               // stable until first barrier releases
    unsigned bar  = 0;

    // --- prologue: convert weights to fp16, zero initial state -------------
    {
        const float4* wc4 = reinterpret_cast<const float4*>(Wc);
        __half2* d = reinterpret_cast<__half2*>(&g_W16[0][0][0]);
        for (int i = gtid; i < 4 * Hn * Hn / 4; i += NCTA * NTHREADS) {
            float4 v = wc4[i];
            d[2 * i]     = __floats2half2_rn(v.x, v.y);
            d[2 * i + 1] = __floats2half2_rn(v.z, v.w);
        }
        const float4* wr4 = reinterpret_cast<const float4*>(Win_rest);
        __half2* d2 = reinterpret_cast<__half2*>(&g_W16[4][0][0]);
        for (int i = gtid; i < 3 * Hn * Hn / 4; i += NCTA * NTHREADS) {
            float4 v = wr4[i];
            d2[2 * i]     = __floats2half2_rn(v.x, v.y);
            d2[2 * i + 1] = __floats2half2_rn(v.z, v.w);
        }
        uint4* z = reinterpret_cast<uint4*>(&g_S16[0][0][0][0]);
        const uint4 z4 = make_uint4(0u, 0u, 0u, 0u);
        for (int i = gtid; i < 4 * Bn * Hn * 2 / 16; i += NCTA * NTHREADS)
            z[i] = z4;
    }
    gbar(base + (++bar));

    // --- wavefront: phase w runs layers j with t = w - j --------------------
    const int slot = cta >> 6;             // 0..3: active-layer slot
    const int tile = cta & 63;             // 64 tiles of 128x64
    const int m0 = (tile >> 3) * 128;      // 8 m-tiles
    const int n0 = (tile & 7) * 64;        // 8 n-tiles

    for (int w = 0; w < Ln + 3; w++) {
        const int jhi = (w < 3) ? w : 3;
        const int jlo = (w > Ln - 1) ? (w - (Ln - 1)) : 0;
        const int nact = jhi - jlo + 1;
        if (slot < nact) {
            const int j = jhi - slot;
            const int t = w - j;
            const int pin = t & 1, pout = pin ^ 1;
            const __half* A1 = &g_S16[pin][j][0][0];
            const __half* A2 = (j > 0) ? &g_S16[pout][j - 1][0][0] : A1;
            const __half* W1 = &g_W16[j][0][0];
            const __half* W2 = (j > 0) ? &g_W16[4 + j - 1][0][0] : W1;
            const float* bias = bc + j * Hn;
            __half* Cout = &g_S16[pout][j][0][0];
            switch (j) {
                case 0:
                    do_job<false, true, false>(&sm, t, A1, A2, W1, W2, bias, x, Win0, Cout, m0, n0);
                    break;
                case 3:
                    do_job<true, false, true>(&sm, t, A1, A2, W1, W2, bias, x, Win0, Cout, m0, n0);
                    break;
                default:
                    do_job<true, false, false>(&sm, t, A1, A2, W1, W2, bias, x, Win0, Cout, m0, n0);
                    break;
            }
        }
        gbar(base + (++bar));
    }
}

// ---------------------------------------------------------------------------
// Log-prob partials: warp (b, tc) handles 8 timesteps, writes g_lp[tc][b].
// ---------------------------------------------------------------------------
__global__ void logp_part(const float* __restrict__ Wout,  // [H][2]
                          const float* __restrict__ bout,  // [2]
                          const int*   __restrict__ xsym)  // [B][L]
{
    const int gw   = (blockIdx.x * blockDim.x + threadIdx.x) >> 5;
    const int lane = threadIdx.x & 31;
    const int b  = gw >> 3;
    const int tc = gw & 7;
    if (b >= Bn) return;

    float w0[16], w1[16];
#pragma unroll
    for (int i = 0; i < 8; i++) {
        const int k = lane * 2 + 64 * i;
        w0[2 * i]     = Wout[k * 2 + 0];
        w1[2 * i]     = Wout[k * 2 + 1];
        w0[2 * i + 1] = Wout[(k + 1) * 2 + 0];
        w1[2 * i + 1] = Wout[(k + 1) * 2 + 1];
    }
    const float b0 = bout[0], b1 = bout[1];

    float acc = 0.f;
#pragma unroll
    for (int tt = 0; tt < 8; tt++) {
        const int t = tc * 8 + tt;
        const __half* h = &g_h16[t][b][0];
        float s0 = 0.f, s1 = 0.f;
#pragma unroll
        for (int i = 0; i < 8; i++) {
            const __half2 hv = *reinterpret_cast<const __half2*>(&h[lane * 2 + 64 * i]);
            const float h0 = __half2float(hv.x);
            const float h1 = __half2float(hv.y);
            s0 += h0 * w0[2 * i] + h1 * w0[2 * i + 1];
            s1 += h0 * w1[2 * i] + h1 * w1[2 * i + 1];
        }
#pragma unroll
        for (int off = 16; off > 0; off >>= 1) {
            s0 += __shfl_xor_sync(0xffffffffu, s0, off);
            s1 += __shfl_xor_sync(0xffffffffu, s1, off);
        }
        s0 += b0; s1 += b1;
        const float m   = fmaxf(s0, s1);
        const float lse = m + logf(expf(s0 - m) + expf(s1 - m));
        const float sel = (xsym[b * Ln + t] == 0) ? s0 : s1;
        acc += sel - lse;
    }
    if (lane == 0) g_lp[tc][b] = acc;
}

// Deterministic final sum: out[b] = 0.5 * sum_tc g_lp[tc][b]
__global__ void logp_sum(float* __restrict__ out) {
    const int b = blockIdx.x * blockDim.x + threadIdx.x;
    if (b >= Bn) return;
    float s = 0.f;
#pragma unroll
    for (int tc = 0; tc < 8; tc++) s += g_lp[tc][b];
    out[b] = 0.5f * s;
}

// ---------------------------------------------------------------------------
extern "C" void kernel_launch(void* const* d_in, const int* in_sizes, int n_in,
                              void* d_out, int out_size) {
    (void)in_sizes; (void)n_in; (void)out_size;
    const int*   x        = (const int*)  d_in[0];  // [B, L]
    const float* Win0     = (const float*)d_in[1];  // [2, H]
    const float* Win_rest = (const float*)d_in[2];  // [3, H, H]
    const float* Wc       = (const float*)d_in[3];  // [4, H, H]
    const float* bc       = (const float*)d_in[4];  // [4, H]
    const float* Wout     = (const float*)d_in[5];  // [H, 2]
    const float* bout     = (const float*)d_in[6];  // [2]
    float* out = (float*)d_out;                     // [B]

    rnn_persistent<<<NCTA, NTHREADS>>>(x, Win0, Win_rest, Wc, bc);
    logp_part<<<(Bn * 8) / 8, 256>>>(Wout, bout, x);   // 1024 blocks, 8 warps each
    logp_sum<<<Bn / 256, 256>>>(out);
}

// round 14
// speedup vs baseline: 1.4896x; 1.1467x over previous
#include <cuda_runtime.h>
#include <cuda_fp16.h>
#include <math.h>

#define Bn 1024
#define Ln 64
#define Hn 512
#define NCTA 256
#define NTHREADS 256

// e4m3 ping-pong state; weights pre-packed in B-fragment order; fp16 history.
__device__ __align__(16) unsigned char g_S8[2][4][Bn][Hn];          // 4 MB
__device__ __align__(16) unsigned char g_W8[7 * 64 * 16 * 32 * 8];  // 1.75 MB
__device__ __half g_h16[Ln][Bn][Hn];     // 64 MB layer-3 outputs
__device__ float  g_lp[8][Bn];           // per-t-chunk partial log-probs
__device__ unsigned g_count;
__device__ volatile unsigned g_gen;

// Smem: A tiles only (B comes from L1-resident fragment-ordered gmem).
struct Smem {
    unsigned char A[2][128][80];   // 128 x 64B tile, pitch 80B (ldsm conflict-free)
};                                 // 20480 B -> 2 CTAs/SM

// ---------------------------------------------------------------------------
__device__ __forceinline__ void cp16(void* dst, const void* src) {
    unsigned d = (unsigned)__cvta_generic_to_shared(dst);
    asm volatile("cp.async.cg.shared.global [%0], [%1], 16;" :: "r"(d), "l"(src));
}
__device__ __forceinline__ void cp_commit() {
    asm volatile("cp.async.commit_group;" ::: "memory");
}
__device__ __forceinline__ void cp_wait0() {
    asm volatile("cp.async.wait_group 0;" ::: "memory");
}
__device__ __forceinline__ void ldsm4(unsigned r[4], const void* p) {
    unsigned a = (unsigned)__cvta_generic_to_shared(p);
    asm volatile("ldmatrix.sync.aligned.m8n8.x4.shared.b16 {%0,%1,%2,%3}, [%4];"
                 : "=r"(r[0]), "=r"(r[1]), "=r"(r[2]), "=r"(r[3]) : "r"(a));
}
// fp8 MMA: m16n8k32, e4m3 x e4m3 -> fp32
__device__ __forceinline__ void mma_f8(float c[4], const unsigned a[4],
                                       unsigned b0, unsigned b1) {
    asm volatile(
        "mma.sync.aligned.m16n8k32.row.col.f32.e4m3.e4m3.f32 "
        "{%0,%1,%2,%3}, {%4,%5,%6,%7}, {%8,%9}, {%0,%1,%2,%3};"
        : "+f"(c[0]), "+f"(c[1]), "+f"(c[2]), "+f"(c[3])
        : "r"(a[0]), "r"(a[1]), "r"(a[2]), "r"(a[3]), "r"(b0), "r"(b1));
}
// pack two floats -> e4m3 pair (lo in low byte)
__device__ __forceinline__ unsigned short pk2(float lo, float hi) {
    unsigned short r;
    asm("cvt.rn.satfinite.e4m3x2.f32 %0, %1, %2;" : "=h"(r) : "f"(hi), "f"(lo));
    return r;
}
__device__ __forceinline__ unsigned pk4(float b0, float b1, float b2, float b3) {
    return (unsigned)pk2(b0, b1) | ((unsigned)pk2(b2, b3) << 16);
}

// Global barrier (R8-proven): 256 CTAs, 2/SM, all co-resident.
__device__ __forceinline__ void gbar(unsigned target) {
    __syncthreads();
    if (threadIdx.x == 0) {
        __threadfence();
        unsigned t = atomicAdd(&g_count, 1);
        if (t == NCTA - 1) {
            atomicExch(&g_count, 0);
            __threadfence();
            g_gen = target;
        } else {
            while ((int)(g_gen - target) < 0) {}
            __threadfence();
        }
    }
    __syncthreads();
}

// Stage one BK=64B A chunk (128 rows x 64B). 2 cp16/thread.
template <bool DUAL>
__device__ __forceinline__ void stage_a(
    Smem* sm, int st, int cc,
    const unsigned char* A1, const unsigned char* A2, int m0, int tid)
{
    const unsigned char* Ap = (DUAL && cc >= 8) ? A2 : A1;
    const int kc = (cc & 7) * 64;
    const int row = tid >> 1;
    const int seg = (tid & 1) * 32;
    const unsigned char* src = Ap + (m0 + row) * Hn + kc + seg;
    cp16(&sm->A[st][row][seg],      src);
    cp16(&sm->A[st][row][seg + 16], src + 16);
}

// One 128x64 job: C = elu(A1@W1 [+ A2@W2] + bias [+ Win0 one-hot row]).
// fp8 m16n8k32 engine; B fragments via LDG.64 from L1-resident g_W8.
template <bool DUAL, bool LAYER0, bool STORE>
__device__ __forceinline__ void do_job(
    Smem* sm, int t,
    const unsigned char* A1, const unsigned char* A2,
    int l1, int l2,
    const float* bias, const int* x, const float* Win0,
    unsigned char* Cout, int m0, int n0)
{
    const int tid  = threadIdx.x;
    const int warp = tid >> 5, lane = tid & 31;
    const int mw = warp >> 1;            // 4 x 32-row blocks
    const int nw = warp & 1;             // 2 x 32-col blocks
    const int quad = lane >> 2, qt = lane & 3;
    const int lrow = lane & 15, lhi = (lane >> 4) * 16;
    const int n8b = (n0 >> 3) + nw * 4;  // first of 4 n8-blocks for this warp

    const uint2* Wf = reinterpret_cast<const uint2*>(g_W8);

    float acc[2][4][4];
#pragma unroll
    for (int a = 0; a < 2; a++)
#pragma unroll
        for (int b = 0; b < 4; b++)
#pragma unroll
            for (int v = 0; v < 4; v++) acc[a][b][v] = 0.f;

    const int NCH = DUAL ? 16 : 8;
    stage_a<DUAL>(sm, 0, 0, A1, A2, m0, tid);
    cp_commit();

    for (int cc = 0; cc < NCH; cc++) {
        cp_wait0();
        __syncthreads();
        const int st = cc & 1;
        if (cc + 1 < NCH)
            stage_a<DUAL>(sm, st ^ 1, cc + 1, A1, A2, m0, tid);
        cp_commit();

        const int lsel = (DUAL && cc >= 8) ? l2 : l1;
#pragma unroll
        for (int ks = 0; ks < 2; ks++) {
            const int kg = (cc & 7) * 2 + ks;    // global k32 index 0..15
            unsigned a[2][4];
            ldsm4(a[0], &sm->A[st][mw * 32 + lrow][ks * 32 + lhi]);
            ldsm4(a[1], &sm->A[st][mw * 32 + 16 + lrow][ks * 32 + lhi]);
            uint2 bv[4];
#pragma unroll
            for (int nb = 0; nb < 4; nb++)
                bv[nb] = Wf[(((lsel * 64) + n8b + nb) * 16 + kg) * 32 + lane];
#pragma unroll
            for (int ma = 0; ma < 2; ma++)
#pragma unroll
                for (int nb = 0; nb < 4; nb++)
                    mma_f8(acc[ma][nb], a[ma], bv[nb].x, bv[nb].y);
        }
    }

    // epilogue: + bias (+ Win0[x[t-1]] row for layer 0), ELU, store
#pragma unroll
    for (int ma = 0; ma < 2; ma++) {
        const int r0 = m0 + mw * 32 + ma * 16 + quad;
        const int r1 = r0 + 8;
        int idx0 = 0, idx1 = 0;
        const bool l0add = LAYER0 && (t > 0);
        if (l0add) {
            idx0 = x[r0 * Ln + (t - 1)];
            idx1 = x[r1 * Ln + (t - 1)];
        }
#pragma unroll
        for (int nb = 0; nb < 4; nb++) {
            const int col = n0 + nw * 32 + nb * 8 + 2 * qt;
            const float2 bv = *reinterpret_cast<const float2*>(&bias[col]);
            float2 w0 = make_float2(0.f, 0.f), w1 = make_float2(0.f, 0.f);
            if (l0add) {
                w0 = *reinterpret_cast<const float2*>(&Win0[idx0 * Hn + col]);
                w1 = *reinterpret_cast<const float2*>(&Win0[idx1 * Hn + col]);
            }
            float v0 = acc[ma][nb][0] + bv.x + w0.x;
            float v1 = acc[ma][nb][1] + bv.y + w0.y;
            float v2 = acc[ma][nb][2] + bv.x + w1.x;
            float v3 = acc[ma][nb][3] + bv.y + w1.y;
            v0 = (v0 > 0.f) ? v0 : expm1f(v0);
            v1 = (v1 > 0.f) ? v1 : expm1f(v1);
            v2 = (v2 > 0.f) ? v2 : expm1f(v2);
            v3 = (v3 > 0.f) ? v3 : expm1f(v3);
            // state: e4m3-rounded carry
            *reinterpret_cast<unsigned short*>(&Cout[r0 * Hn + col]) = pk2(v0, v1);
            *reinterpret_cast<unsigned short*>(&Cout[r1 * Hn + col]) = pk2(v2, v3);
            if (STORE) {
                // history: fp16 from fp32 epilogue (logp path unchanged)
                *reinterpret_cast<__half2*>(&g_h16[t][r0][col]) = __floats2half2_rn(v0, v1);
                *reinterpret_cast<__half2*>(&g_h16[t][r1][col]) = __floats2half2_rn(v2, v3);
            }
        }
    }
}

// ---------------------------------------------------------------------------
__global__ void __launch_bounds__(NTHREADS, 2) rnn_persistent(
    const int*   __restrict__ x,         // [B][L]
    const float* __restrict__ Win0,      // [2][H]
    const float* __restrict__ Win_rest,  // [3][H][H]
    const float* __restrict__ Wc,        // [4][H][H]
    const float* __restrict__ bc)        // [4][H]
{
    __shared__ __align__(16) Smem sm;

    const int tid  = threadIdx.x;
    const int cta  = blockIdx.x;
    const int gtid = cta * NTHREADS + tid;

    unsigned base = g_gen;               // stable until first barrier releases
    unsigned bar  = 0;

    // --- prologue: pack weights to e4m3 B-fragment order; zero state --------
    {
        unsigned* W32 = reinterpret_cast<unsigned*>(g_W8);
        const int NW = 7 * 64 * 16 * 32 * 2;   // u32 words
        for (int w = gtid; w < NW; w += NCTA * NTHREADS) {
            const int reg  = w & 1;
            const int lane = (w >> 1) & 31;
            const int kc   = (w >> 6) & 15;
            const int n8   = (w >> 10) & 63;
            const int l    = w >> 16;
            const int k = kc * 32 + (lane & 3) * 4 + reg * 16;
            const int n = n8 * 8 + (lane >> 2);
            const float* Wsrc = (l < 4) ? (Wc + l * Hn * Hn)
                                        : (Win_rest + (l - 4) * Hn * Hn);
            const float f0 = Wsrc[(k + 0) * Hn + n];
            const float f1 = Wsrc[(k + 1) * Hn + n];
            const float f2 = Wsrc[(k + 2) * Hn + n];
            const float f3 = Wsrc[(k + 3) * Hn + n];
            W32[w] = pk4(f0, f1, f2, f3);
        }
        uint4* z = reinterpret_cast<uint4*>(&g_S8[0][0][0][0]);
        const uint4 z4 = make_uint4(0u, 0u, 0u, 0u);
        for (int i = gtid; i < 2 * 4 * Bn * Hn / 16; i += NCTA * NTHREADS)
            z[i] = z4;
    }
    gbar(base + (++bar));

    // --- wavefront: phase w runs layers j with t = w - j --------------------
    const int slot = cta >> 6;             // 0..3: active-layer slot
    const int tile = cta & 63;             // 64 tiles of 128x64
    const int m0 = (tile >> 3) * 128;      // 8 m-tiles
    const int n0 = (tile & 7) * 64;        // 8 n-tiles

    for (int w = 0; w < Ln + 3; w++) {
        const int jhi = (w < 3) ? w : 3;
        const int jlo = (w > Ln - 1) ? (w - (Ln - 1)) : 0;
        const int nact = jhi - jlo + 1;
        if (slot < nact) {
            const int j = jhi - slot;
            const int t = w - j;
            const int pin = t & 1, pout = pin ^ 1;
            const unsigned char* A1 = &g_S8[pin][j][0][0];
            const unsigned char* A2 = (j > 0) ? &g_S8[pout][j - 1][0][0] : A1;
            const int l1 = j;                       // Wc_j
            const int l2 = (j > 0) ? (4 + j - 1) : j;  // Win_j
            const float* bias = bc + j * Hn;
            unsigned char* Cout = &g_S8[pout][j][0][0];
            switch (j) {
                case 0:
                    do_job<false, true, false>(&sm, t, A1, A2, l1, l2, bias, x, Win0, Cout, m0, n0);
                    break;
                case 3:
                    do_job<true, false, true>(&sm, t, A1, A2, l1, l2, bias, x, Win0, Cout, m0, n0);
                    break;
                default:
                    do_job<true, false, false>(&sm, t, A1, A2, l1, l2, bias, x, Win0, Cout, m0, n0);
                    break;
            }
        }
        gbar(base + (++bar));
    }
}

// ---------------------------------------------------------------------------
// Log-prob partials: warp (b, tc) handles 8 timesteps, writes g_lp[tc][b].
// ---------------------------------------------------------------------------
__global__ void logp_part(const float* __restrict__ Wout,  // [H][2]
                          const float* __restrict__ bout,  // [2]
                          const int*   __restrict__ xsym)  // [B][L]
{
    const int gw   = (blockIdx.x * blockDim.x + threadIdx.x) >> 5;
    const int lane = threadIdx.x & 31;
    const int b  = gw >> 3;
    const int tc = gw & 7;
    if (b >= Bn) return;

    float w0[16], w1[16];
#pragma unroll
    for (int i = 0; i < 8; i++) {
        const int k = lane * 2 + 64 * i;
        w0[2 * i]     = Wout[k * 2 + 0];
        w1[2 * i]     = Wout[k * 2 + 1];
        w0[2 * i + 1] = Wout[(k + 1) * 2 + 0];
        w1[2 * i + 1] = Wout[(k + 1) * 2 + 1];
    }
    const float b0 = bout[0], b1 = bout[1];

    float acc = 0.f;
#pragma unroll
    for (int tt = 0; tt < 8; tt++) {
        const int t = tc * 8 + tt;
        const __half* h = &g_h16[t][b][0];
        float s0 = 0.f, s1 = 0.f;
#pragma unroll
        for (int i = 0; i < 8; i++) {
            const __half2 hv = *reinterpret_cast<const __half2*>(&h[lane * 2 + 64 * i]);
            const float h0 = __half2float(hv.x);
            const float h1 = __half2float(hv.y);
            s0 += h0 * w0[2 * i] + h1 * w0[2 * i + 1];
            s1 += h0 * w1[2 * i] + h1 * w1[2 * i + 1];
        }
#pragma unroll
        for (int off = 16; off > 0; off >>= 1) {
            s0 += __shfl_xor_sync(0xffffffffu, s0, off);
            s1 += __shfl_xor_sync(0xffffffffu, s1, off);
        }
        s0 += b0; s1 += b1;
        const float m   = fmaxf(s0, s1);
        const float lse = m + logf(expf(s0 - m) + expf(s1 - m));
        const float sel = (xsym[b * Ln + t] == 0) ? s0 : s1;
        acc += sel - lse;
    }
    if (lane == 0) g_lp[tc][b] = acc;
}

// Deterministic final sum: out[b] = 0.5 * sum_tc g_lp[tc][b]
__global__ void logp_sum(float* __restrict__ out) {
    const int b = blockIdx.x * blockDim.x + threadIdx.x;
    if (b >= Bn) return;
    float s = 0.f;
#pragma unroll
    for (int tc = 0; tc < 8; tc++) s += g_lp[tc][b];
    out[b] = 0.5f * s;
}

// ---------------------------------------------------------------------------
extern "C" void kernel_launch(void* const* d_in, const int* in_sizes, int n_in,
                              void* d_out, int out_size) {
    (void)in_sizes; (void)n_in; (void)out_size;
    const int*   x        = (const int*)  d_in[0];  // [B, L]
    const float* Win0     = (const float*)d_in[1];  // [2, H]
    const float* Win_rest = (const float*)d_in[2];  // [3, H, H]
    const float* Wc       = (const float*)d_in[3];  // [4, H, H]
    const float* bc       = (const float*)d_in[4];  // [4, H]
    const float* Wout     = (const float*)d_in[5];  // [H, 2]
    const float* bout     = (const float*)d_in[6];  // [2]
    float* out = (float*)d_out;                     // [B]

    rnn_persistent<<<NCTA, NTHREADS>>>(x, Win0, Win_rest, Wc, bc);
    logp_part<<<(Bn * 8) / 8, 256>>>(Wout, bout, x);   // 1024 blocks, 8 warps each
    logp_sum<<<Bn / 256, 256>>>(out);
}

// round 15
// speedup vs baseline: 1.5421x; 1.0352x over previous
#include <cuda_runtime.h>
#include <cuda_fp16.h>
#include <math.h>

#define Bn 1024
#define Ln 64
#define Hn 512
#define NCTA 256
#define NTHREADS 256

// e4m3 state stored in A-FRAGMENT order (m16n8k32): [parity][layer][mb(64)][k32(16)][512B]
__device__ __align__(16) unsigned char g_S8[2][4][64][16][512];     // 4 MB
// weights in B-fragment order (R14-proven): [layer7][n8(64)][k32(16)][lane(32)][8B]
__device__ __align__(16) unsigned char g_W8[7 * 64 * 16 * 32 * 8];  // 1.75 MB
__device__ __half g_h16[Ln][Bn][Hn];     // 64 MB layer-3 outputs (linear, logp path)
__device__ float  g_lp[8][Bn];           // per-t-chunk partial log-probs
__device__ unsigned g_count;
__device__ volatile unsigned g_gen;

// ---------------------------------------------------------------------------
// fp8 MMA: m16n8k32, e4m3 x e4m3 -> fp32
__device__ __forceinline__ void mma_f8(float c[4], const uint4 a,
                                       unsigned b0, unsigned b1) {
    asm volatile(
        "mma.sync.aligned.m16n8k32.row.col.f32.e4m3.e4m3.f32 "
        "{%0,%1,%2,%3}, {%4,%5,%6,%7}, {%8,%9}, {%0,%1,%2,%3};"
        : "+f"(c[0]), "+f"(c[1]), "+f"(c[2]), "+f"(c[3])
        : "r"(a.x), "r"(a.y), "r"(a.z), "r"(a.w), "r"(b0), "r"(b1));
}
// pack two floats -> e4m3 pair (lo in low byte)
__device__ __forceinline__ unsigned short pk2(float lo, float hi) {
    unsigned short r;
    asm("cvt.rn.satfinite.e4m3x2.f32 %0, %1, %2;" : "=h"(r) : "f"(hi), "f"(lo));
    return r;
}
__device__ __forceinline__ unsigned pk4(float b0, float b1, float b2, float b3) {
    return (unsigned)pk2(b0, b1) | ((unsigned)pk2(b2, b3) << 16);
}

// Global barrier (R8-proven): 256 CTAs, 2/SM, all co-resident.
__device__ __forceinline__ void gbar(unsigned target) {
    __syncthreads();
    if (threadIdx.x == 0) {
        __threadfence();
        unsigned t = atomicAdd(&g_count, 1);
        if (t == NCTA - 1) {
            atomicExch(&g_count, 0);
            __threadfence();
            g_gen = target;
        } else {
            while ((int)(g_gen - target) < 0) {}
            __threadfence();
        }
    }
    __syncthreads();
}

// One 128x64 job, fully smem-free:
//   A fragments: LDG.128 from fragment-ordered state (L1/L2, deep MLP)
//   B fragments: LDG.64 from fragment-ordered weights (L1-resident)
// C = elu(A1@W1 [+ A2@W2] + bias [+ Win0 one-hot row]); state written back
// in A-fragment order; layer-3 also writes linear fp16 history.
template <bool DUAL, bool LAYER0, bool STORE>
__device__ __forceinline__ void do_job(
    int t,
    const uint4* __restrict__ A1f, const uint4* __restrict__ A2f,
    int l1, int l2,
    const float* __restrict__ bias, const int* __restrict__ x,
    const float* __restrict__ Win0,
    unsigned char* __restrict__ Cout,   // fragment-ordered state out
    int m0, int n0)
{
    const int tid  = threadIdx.x;
    const int warp = tid >> 5, lane = tid & 31;
    const int mw = warp >> 1;            // 4 x 32-row blocks
    const int nw = warp & 1;             // 2 x 32-col blocks
    const int quad = lane >> 2, qt = lane & 3;
    const int n8b = (n0 >> 3) + nw * 4;  // first of 4 n8-blocks for this warp
    const int mb0 = (m0 >> 4) + mw * 2;  // fragment-row blocks (mb0, mb0+1)

    const uint2* Wf = reinterpret_cast<const uint2*>(g_W8);

    float acc[2][4][4];
#pragma unroll
    for (int a = 0; a < 2; a++)
#pragma unroll
        for (int b = 0; b < 4; b++)
#pragma unroll
            for (int v = 0; v < 4; v++) acc[a][b][v] = 0.f;

    const int NKG = DUAL ? 32 : 16;
#pragma unroll 8
    for (int kg = 0; kg < NKG; kg++) {
        const bool ph = DUAL && (kg >= 16);
        const uint4* Af = ph ? A2f : A1f;
        const int lsel = ph ? l2 : l1;
        const int kk = kg & 15;

        const uint4 a0 = Af[((mb0 + 0) * 16 + kk) * 32 + lane];
        const uint4 a1 = Af[((mb0 + 1) * 16 + kk) * 32 + lane];
        uint2 bv[4];
#pragma unroll
        for (int nb = 0; nb < 4; nb++)
            bv[nb] = Wf[(((lsel * 64) + n8b + nb) * 16 + kk) * 32 + lane];

#pragma unroll
        for (int nb = 0; nb < 4; nb++) {
            mma_f8(acc[0][nb], a0, bv[nb].x, bv[nb].y);
            mma_f8(acc[1][nb], a1, bv[nb].x, bv[nb].y);
        }
    }

    // epilogue: + bias (+ Win0[x[t-1]] row for layer 0), ELU, store fragments
#pragma unroll
    for (int ma = 0; ma < 2; ma++) {
        const int r0 = m0 + mw * 32 + ma * 16 + quad;     // rows r0, r0+8
        const int mb = mb0 + ma;
        int idx0 = 0, idx1 = 0;
        const bool l0add = LAYER0 && (t > 0);
        if (l0add) {
            idx0 = x[r0 * Ln + (t - 1)];
            idx1 = x[(r0 + 8) * Ln + (t - 1)];
        }
#pragma unroll
        for (int nb = 0; nb < 4; nb++) {
            const int col = n0 + nw * 32 + nb * 8 + 2 * qt;
            const float2 bv = *reinterpret_cast<const float2*>(&bias[col]);
            float2 w0 = make_float2(0.f, 0.f), w1 = make_float2(0.f, 0.f);
            if (l0add) {
                w0 = *reinterpret_cast<const float2*>(&Win0[idx0 * Hn + col]);
                w1 = *reinterpret_cast<const float2*>(&Win0[idx1 * Hn + col]);
            }
            float v0 = acc[ma][nb][0] + bv.x + w0.x;
            float v1 = acc[ma][nb][1] + bv.y + w0.y;
            float v2 = acc[ma][nb][2] + bv.x + w1.x;
            float v3 = acc[ma][nb][3] + bv.y + w1.y;
            v0 = (v0 > 0.f) ? v0 : expm1f(v0);
            v1 = (v1 > 0.f) ? v1 : expm1f(v1);
            v2 = (v2 > 0.f) ? v2 : expm1f(v2);
            v3 = (v3 > 0.f) ? v3 : expm1f(v3);

            // fragment-order state store:
            //   lane' = (r&7)*4 + ((col>>2)&3); byte = (rloc>>3)*4 + ((col>>4)&1)*8 + (col&3)
            const int k32   = col >> 5;
            const int lanep = quad * 4 + ((col >> 2) & 3);
            const int bhi   = ((col >> 4) & 1) * 8 + (col & 3);
            unsigned char* fb = Cout + ((mb * 16 + k32) * 32 + lanep) * 16 + bhi;
            *reinterpret_cast<unsigned short*>(fb)     = pk2(v0, v1);   // row r0  (rloc<8)
            *reinterpret_cast<unsigned short*>(fb + 4) = pk2(v2, v3);   // row r0+8
            if (STORE) {
                *reinterpret_cast<__half2*>(&g_h16[t][r0][col])     = __floats2half2_rn(v0, v1);
                *reinterpret_cast<__half2*>(&g_h16[t][r0 + 8][col]) = __floats2half2_rn(v2, v3);
            }
        }
    }
}

// ---------------------------------------------------------------------------
__global__ void __launch_bounds__(NTHREADS, 2) rnn_persistent(
    const int*   __restrict__ x,         // [B][L]
    const float* __restrict__ Win0,      // [2][H]
    const float* __restrict__ Win_rest,  // [3][H][H]
    const float* __restrict__ Wc,        // [4][H][H]
    const float* __restrict__ bc)        // [4][H]
{
    const int tid  = threadIdx.x;
    const int cta  = blockIdx.x;
    const int gtid = cta * NTHREADS + tid;

    unsigned base = g_gen;               // stable until first barrier releases
    unsigned bar  = 0;

    // --- prologue: pack weights to e4m3 B-fragment order; zero state --------
    {
        unsigned* W32 = reinterpret_cast<unsigned*>(g_W8);
        const int NW = 7 * 64 * 16 * 32 * 2;   // u32 words
        for (int w = gtid; w < NW; w += NCTA * NTHREADS) {
            const int reg  = w & 1;
            const int lane = (w >> 1) & 31;
            const int kc   = (w >> 6) & 15;
            const int n8   = (w >> 10) & 63;
            const int l    = w >> 16;
            const int k = kc * 32 + (lane & 3) * 4 + reg * 16;
            const int n = n8 * 8 + (lane >> 2);
            const float* Wsrc = (l < 4) ? (Wc + l * Hn * Hn)
                                        : (Win_rest + (l - 4) * Hn * Hn);
            const float f0 = Wsrc[(k + 0) * Hn + n];
            const float f1 = Wsrc[(k + 1) * Hn + n];
            const float f2 = Wsrc[(k + 2) * Hn + n];
            const float f3 = Wsrc[(k + 3) * Hn + n];
            W32[w] = pk4(f0, f1, f2, f3);
        }
        uint4* z = reinterpret_cast<uint4*>(&g_S8[0][0][0][0][0]);
        const uint4 z4 = make_uint4(0u, 0u, 0u, 0u);
        for (int i = gtid; i < 2 * 4 * Bn * Hn / 16; i += NCTA * NTHREADS)
            z[i] = z4;
    }
    gbar(base + (++bar));

    // --- wavefront: phase w runs layers j with t = w - j --------------------
    const int slot = cta >> 6;             // 0..3: active-layer slot
    const int tile = cta & 63;             // 64 tiles of 128x64
    const int m0 = (tile >> 3) * 128;      // 8 m-tiles
    const int n0 = (tile & 7) * 64;        // 8 n-tiles

    for (int w = 0; w < Ln + 3; w++) {
        const int jhi = (w < 3) ? w : 3;
        const int jlo = (w > Ln - 1) ? (w - (Ln - 1)) : 0;
        const int nact = jhi - jlo + 1;
        if (slot < nact) {
            const int j = jhi - slot;
            const int t = w - j;
            const int pin = t & 1, pout = pin ^ 1;
            const uint4* A1f = reinterpret_cast<const uint4*>(&g_S8[pin][j][0][0][0]);
            const uint4* A2f = (j > 0)
                ? reinterpret_cast<const uint4*>(&g_S8[pout][j - 1][0][0][0]) : A1f;
            const int l1 = j;
            const int l2 = (j > 0) ? (4 + j - 1) : j;
            const float* bias = bc + j * Hn;
            unsigned char* Cout = &g_S8[pout][j][0][0][0];
            switch (j) {
                case 0:
                    do_job<false, true, false>(t, A1f, A2f, l1, l2, bias, x, Win0, Cout, m0, n0);
                    break;
                case 3:
                    do_job<true, false, true>(t, A1f, A2f, l1, l2, bias, x, Win0, Cout, m0, n0);
                    break;
                default:
                    do_job<true, false, false>(t, A1f, A2f, l1, l2, bias, x, Win0, Cout, m0, n0);
                    break;
            }
        }
        gbar(base + (++bar));
    }
}

// ---------------------------------------------------------------------------
// Log-prob partials: warp (b, tc) handles 8 timesteps, writes g_lp[tc][b].
// ---------------------------------------------------------------------------
__global__ void logp_part(const float* __restrict__ Wout,  // [H][2]
                          const float* __restrict__ bout,  // [2]
                          const int*   __restrict__ xsym)  // [B][L]
{
    const int gw   = (blockIdx.x * blockDim.x + threadIdx.x) >> 5;
    const int lane = threadIdx.x & 31;
    const int b  = gw >> 3;
    const int tc = gw & 7;
    if (b >= Bn) return;

    float w0[16], w1[16];
#pragma unroll
    for (int i = 0; i < 8; i++) {
        const int k = lane * 2 + 64 * i;
        w0[2 * i]     = Wout[k * 2 + 0];
        w1[2 * i]     = Wout[k * 2 + 1];
        w0[2 * i + 1] = Wout[(k + 1) * 2 + 0];
        w1[2 * i + 1] = Wout[(k + 1) * 2 + 1];
    }
    const float b0 = bout[0], b1 = bout[1];

    float acc = 0.f;
#pragma unroll
    for (int tt = 0; tt < 8; tt++) {
        const int t = tc * 8 + tt;
        const __half* h = &g_h16[t][b][0];
        float s0 = 0.f, s1 = 0.f;
#pragma unroll
        for (int i = 0; i < 8; i++) {
            const __half2 hv = *reinterpret_cast<const __half2*>(&h[lane * 2 + 64 * i]);
            const float h0 = __half2float(hv.x);
            const float h1 = __half2float(hv.y);
            s0 += h0 * w0[2 * i] + h1 * w0[2 * i + 1];
            s1 += h0 * w1[2 * i] + h1 * w1[2 * i + 1];
        }
#pragma unroll
        for (int off = 16; off > 0; off >>= 1) {
            s0 += __shfl_xor_sync(0xffffffffu, s0, off);
            s1 += __shfl_xor_sync(0xffffffffu, s1, off);
        }
        s0 += b0; s1 += b1;
        const float m   = fmaxf(s0, s1);
        const float lse = m + logf(expf(s0 - m) + expf(s1 - m));
        const float sel = (xsym[b * Ln + t] == 0) ? s0 : s1;
        acc += sel - lse;
    }
    if (lane == 0) g_lp[tc][b] = acc;
}

// Deterministic final sum: out[b] = 0.5 * sum_tc g_lp[tc][b]
__global__ void logp_sum(float* __restrict__ out) {
    const int b = blockIdx.x * blockDim.x + threadIdx.x;
    if (b >= Bn) return;
    float s = 0.f;
#pragma unroll
    for (int tc = 0; tc < 8; tc++) s += g_lp[tc][b];
    out[b] = 0.5f * s;
}

// ---------------------------------------------------------------------------
extern "C" void kernel_launch(void* const* d_in, const int* in_sizes, int n_in,
                              void* d_out, int out_size) {
    (void)in_sizes; (void)n_in; (void)out_size;
    const int*   x        = (const int*)  d_in[0];  // [B, L]
    const float* Win0     = (const float*)d_in[1];  // [2, H]
    const float* Win_rest = (const float*)d_in[2];  // [3, H, H]
    const float* Wc       = (const float*)d_in[3];  // [4, H, H]
    const float* bc       = (const float*)d_in[4];  // [4, H]
    const float* Wout     = (const float*)d_in[5];  // [H, 2]
    const float* bout     = (const float*)d_in[6];  // [2]
    float* out = (float*)d_out;                     // [B]

    rnn_persistent<<<NCTA, NTHREADS>>>(x, Win0, Win_rest, Wc, bc);
    logp_part<<<(Bn * 8) / 8, 256>>>(Wout, bout, x);   // 1024 blocks, 8 warps each
    logp_sum<<<Bn / 256, 256>>>(out);
}